// round 10
// baseline (speedup 1.0000x reference)
#include <cuda_runtime.h>
#include <cuda_bf16.h>
#include <cuda_fp16.h>
#include <cstdint>

// Shapes (fixed)
#define NB 4
#define NQ 512
#define NK 512
#define ND 256
#define NH 256

#define STRIDE 260   // smem row stride (floats): conflict-free LDS.128

__device__ float g_qh[NB * NQ * NH];
__device__ float g_kh[NB * NK * NH];

// two tanh per MUFU op
__device__ __forceinline__ unsigned tanh2_ap(unsigned x) {
    unsigned y;
    asm("tanh.approx.f16x2 %0, %1;" : "=r"(y) : "r"(x));
    return y;
}

// ---------------------------------------------------------------------------
// Projection GEMM: C[2048x256] = A[2048x256] @ W[256x256]  (unchanged)
// ---------------------------------------------------------------------------
__global__ __launch_bounds__(256) void proj_kernel(
    const float* __restrict__ Aq, const float* __restrict__ Wq,
    const float* __restrict__ Ak, const float* __restrict__ Wk)
{
    const float* A; const float* W; float* C;
    if (blockIdx.z == 0) { A = Aq; W = Wq; C = g_qh; }
    else                 { A = Ak; W = Wk; C = g_kh; }

    __shared__ float As[16][68];
    __shared__ float Bs[16][68];

    const int t    = threadIdx.x;
    const int row0 = blockIdx.y * 64;
    const int col0 = blockIdx.x * 64;
    const int ty   = t >> 4;
    const int tx   = t & 15;

    float acc[4][4] = {};

    for (int k0 = 0; k0 < ND; k0 += 16) {
        {
            int r  = t >> 2;
            int c4 = (t & 3) * 4;
            float4 v = *(const float4*)&A[(row0 + r) * ND + k0 + c4];
            As[c4 + 0][r] = v.x;
            As[c4 + 1][r] = v.y;
            As[c4 + 2][r] = v.z;
            As[c4 + 3][r] = v.w;
        }
        {
            int r  = t >> 4;
            int c4 = (t & 15) * 4;
            *(float4*)&Bs[r][c4] = *(const float4*)&W[(k0 + r) * NH + col0 + c4];
        }
        __syncthreads();
        #pragma unroll
        for (int kk = 0; kk < 16; kk++) {
            float4 av = *(float4*)&As[kk][ty * 4];
            float4 bv = *(float4*)&Bs[kk][tx * 4];
            float a_[4] = {av.x, av.y, av.z, av.w};
            float b_[4] = {bv.x, bv.y, bv.z, bv.w};
            #pragma unroll
            for (int i = 0; i < 4; i++)
                #pragma unroll
                for (int j = 0; j < 4; j++)
                    acc[i][j] += a_[i] * b_[j];
        }
        __syncthreads();
    }

    #pragma unroll
    for (int i = 0; i < 4; i++) {
        float4 v = make_float4(acc[i][0], acc[i][1], acc[i][2], acc[i][3]);
        *(float4*)&C[(row0 + ty * 4 + i) * NH + col0 + tx * 4] = v;
    }
}

// ---------------------------------------------------------------------------
// Fused attention (R1 structure + batch interleave + f16x2 tanh).
// 256 blocks x 256 threads = 8 warps = 8 queries of batch (blockIdx & 3).
// ---------------------------------------------------------------------------
__global__ __launch_bounds__(256, 2) void attn_kernel(
    const float* __restrict__ values,
    const float* __restrict__ wv,
    const int*   __restrict__ valid_lens,
    float*       __restrict__ out)
{
    __shared__ float sbuf[32 * STRIDE];    // 33280 B: kh tiles (A) / values tiles (C)
    __shared__ float s_qh[8 * NH];         // 8192 B
    __shared__ float s_wv[NH];             // 1024 B
    float* attn_s = &sbuf[16 * STRIDE];    // 8*512 floats, disjoint from 16-key values tile

    const int t    = threadIdx.x;
    const int w    = t >> 5;
    const int lane = t & 31;
    const int b    = blockIdx.x & 3;               // batch-interleaved
    const int qblk = blockIdx.x >> 2;              // 0..63
    const int vl   = valid_lens[b];                // uniform across block

    // Stage qh rows for this block's 8 queries + wv
    #pragma unroll
    for (int rr = 0; rr < 2; rr++) {
        int i = t + 256 * rr;                      // 0..511 float4 slots
        int r = i >> 6;
        int c = (i & 63) * 4;
        *(float4*)&s_qh[r * NH + c] =
            *(const float4*)&g_qh[(b * NQ + qblk * 8 + r) * NH + c];
    }
    if (t < 64) *(float4*)&s_wv[t * 4] = *(const float4*)&wv[t * 4];
    __syncthreads();

    // ---------------- Phase A: scores ----------------
    float sc[16];
    #pragma unroll
    for (int i = 0; i < 16; i++) sc[i] = -1.0e6f;

    const float* khb = &g_kh[(b * NK) * NH];
    const float* myq = &s_qh[w * NH];

    #pragma unroll
    for (int tile = 0; tile < 16; ++tile) {
        if (tile * 32 < vl) {                      // uniform branch (vl per-block)
            // load kh tile: 32 keys x 256 h  (2048 float4, 8 per thread)
            #pragma unroll
            for (int r = 0; r < 8; ++r) {
                int i  = t + 256 * r;
                int k  = i >> 6;
                int h4 = (i & 63) * 4;
                *(float4*)&sbuf[k * STRIDE + h4] =
                    *(const float4*)&khb[(tile * 32 + k) * NH + h4];
            }
            __syncthreads();

            float a0 = 0.f, a1 = 0.f, a2 = 0.f, a3 = 0.f;
            const float* myk = &sbuf[lane * STRIDE];
            #pragma unroll 4
            for (int h = 0; h < NH; h += 4) {
                float4 kv  = *(const float4*)&myk[h];
                float4 qv  = *(const float4*)&myq[h];    // broadcast
                float4 wv4 = *(const float4*)&s_wv[h];   // broadcast
                __half2 x01 = __floats2half2_rn(qv.x + kv.x, qv.y + kv.y);
                __half2 x23 = __floats2half2_rn(qv.z + kv.z, qv.w + kv.w);
                unsigned u01 = tanh2_ap(*reinterpret_cast<unsigned*>(&x01));
                unsigned u23 = tanh2_ap(*reinterpret_cast<unsigned*>(&x23));
                __half2 t01 = *reinterpret_cast<__half2*>(&u01);
                __half2 t23 = *reinterpret_cast<__half2*>(&u23);
                a0 += wv4.x * __low2float(t01);
                a1 += wv4.y * __high2float(t01);
                a2 += wv4.z * __low2float(t23);
                a3 += wv4.w * __high2float(t23);
            }
            sc[tile] = (a0 + a1) + (a2 + a3);      // key = tile*32 + lane
            __syncthreads();
        }
    }

    // mask tail keys of the partial tile
    #pragma unroll
    for (int i = 0; i < 16; i++) {
        int k = i * 32 + lane;
        if (k >= vl) sc[i] = -1.0e6f;
    }

    __syncthreads();   // everyone done reading sbuf before attn_s writes overlay it

    // ---------------- Phase B: softmax (registers + shuffles) ----------------
    float mx = -1.0e30f;
    #pragma unroll
    for (int i = 0; i < 16; i++) mx = fmaxf(mx, sc[i]);
    #pragma unroll
    for (int o = 16; o > 0; o >>= 1)
        mx = fmaxf(mx, __shfl_xor_sync(0xffffffffu, mx, o));

    float sum = 0.f;
    #pragma unroll
    for (int i = 0; i < 16; i++) {
        float e = __expf(sc[i] - mx);              // masked -> exact 0 (underflow)
        sum += e;
        attn_s[w * NK + i * 32 + lane] = e;        // unnormalized
    }
    #pragma unroll
    for (int o = 16; o > 0; o >>= 1)
        sum += __shfl_xor_sync(0xffffffffu, sum, o);
    const float inv = 1.0f / sum;

    // ---------------- Phase C: out = attn @ values ----------------
    float4 o0 = make_float4(0.f, 0.f, 0.f, 0.f);
    float4 o1 = make_float4(0.f, 0.f, 0.f, 0.f);
    const int nTilesC = (vl + 15) >> 4;
    const float* vb = &values[(b * NK) * ND];

    for (int tile = 0; tile < nTilesC; ++tile) {
        __syncthreads();                           // tile t reads done / attn_s ready
        // load values tile: 16 keys x 256 d (1024 float4, 4 per thread)
        #pragma unroll
        for (int r = 0; r < 4; ++r) {
            int i  = t + 256 * r;
            int k  = i >> 6;
            int h4 = (i & 63) * 4;
            *(float4*)&sbuf[k * STRIDE + h4] =
                *(const float4*)&vb[(tile * 16 + k) * ND + h4];
        }
        __syncthreads();

        #pragma unroll 4
        for (int kk = 0; kk < 16; ++kk) {
            float a = attn_s[w * NK + tile * 16 + kk];        // broadcast
            float4 v0 = *(const float4*)&sbuf[kk * STRIDE + 4 * lane];
            float4 v1 = *(const float4*)&sbuf[kk * STRIDE + 128 + 4 * lane];
            o0.x += a * v0.x; o0.y += a * v0.y; o0.z += a * v0.z; o0.w += a * v0.w;
            o1.x += a * v1.x; o1.y += a * v1.y; o1.z += a * v1.z; o1.w += a * v1.w;
        }
    }

    o0.x *= inv; o0.y *= inv; o0.z *= inv; o0.w *= inv;
    o1.x *= inv; o1.y *= inv; o1.z *= inv; o1.w *= inv;
    const int qrow = b * NQ + qblk * 8 + w;
    *(float4*)&out[qrow * ND + 4 * lane]       = o0;
    *(float4*)&out[qrow * ND + 128 + 4 * lane] = o1;
}

// ---------------------------------------------------------------------------
extern "C" void kernel_launch(void* const* d_in, const int* in_sizes, int n_in,
                              void* d_out, int out_size)
{
    const float* queries = (const float*)d_in[0];
    const float* keys    = (const float*)d_in[1];
    const float* values  = (const float*)d_in[2];
    const float* Wq      = (const float*)d_in[3];
    const float* Wk      = (const float*)d_in[4];
    const float* wv      = (const float*)d_in[5];
    const int*   vlen    = (const int*)d_in[6];
    float* out = (float*)d_out;

    (void)in_sizes; (void)n_in; (void)out_size;

    dim3 pgrid(NH / 64, (NB * NQ) / 64, 2);
    proj_kernel<<<pgrid, 256>>>(queries, Wq, keys, Wk);

    attn_kernel<<<(NB * NQ) / 8, 256>>>(values, wv, vlen, out);
}

// round 11
// speedup vs baseline: 1.0820x; 1.0820x over previous
#include <cuda_runtime.h>
#include <cuda_fp16.h>
#include <cstdint>

// Shapes (fixed)
#define NB 4
#define NQ 512
#define NK 512
#define ND 256
#define NH 256

#define ROWW 132   // words (uint32) per padded smem tile row: 128 data + 4 pad -> conflict-free

__device__ float  g_qh[NB * NQ * NH];   // projected queries, f32
__device__ __half g_kh[NB * NK * NH];   // projected keys, f16
__device__ __half g_vh[NB * NK * ND];   // values, f16

__device__ __forceinline__ unsigned hadd2_u(unsigned a, unsigned b) {
    unsigned r; asm("add.rn.f16x2 %0, %1, %2;" : "=r"(r) : "r"(a), "r"(b)); return r;
}
__device__ __forceinline__ unsigned tanh2_u(unsigned x) {
    unsigned r; asm("tanh.approx.f16x2 %0, %1;" : "=r"(r) : "r"(x)); return r;
}
__device__ __forceinline__ float2 h2f2(unsigned h) {
    __half2 hh = *reinterpret_cast<__half2*>(&h);
    return __half22float2(hh);
}
__device__ __forceinline__ unsigned f2h2(float lo, float hi) {
    __half2 hh = __floats2half2_rn(lo, hi);
    return *reinterpret_cast<unsigned*>(&hh);
}

// ---------------------------------------------------------------------------
// Projection GEMM: C[2048x256] = A[2048x256] @ W[256x256]
// z = 0 -> g_qh (f32), z = 1 -> g_kh (f16 epilogue)
// ---------------------------------------------------------------------------
__global__ __launch_bounds__(256) void proj_kernel(
    const float* __restrict__ Aq, const float* __restrict__ Wq,
    const float* __restrict__ Ak, const float* __restrict__ Wk)
{
    const float* A; const float* W;
    if (blockIdx.z == 0) { A = Aq; W = Wq; }
    else                 { A = Ak; W = Wk; }

    __shared__ float As[16][68];
    __shared__ float Bs[16][68];

    const int t    = threadIdx.x;
    const int row0 = blockIdx.y * 64;
    const int col0 = blockIdx.x * 64;
    const int ty   = t >> 4;
    const int tx   = t & 15;

    float acc[4][4] = {};

    for (int k0 = 0; k0 < ND; k0 += 16) {
        {
            int r  = t >> 2;
            int c4 = (t & 3) * 4;
            float4 v = *(const float4*)&A[(row0 + r) * ND + k0 + c4];
            As[c4 + 0][r] = v.x;
            As[c4 + 1][r] = v.y;
            As[c4 + 2][r] = v.z;
            As[c4 + 3][r] = v.w;
        }
        {
            int r  = t >> 4;
            int c4 = (t & 15) * 4;
            *(float4*)&Bs[r][c4] = *(const float4*)&W[(k0 + r) * NH + col0 + c4];
        }
        __syncthreads();
        #pragma unroll
        for (int kk = 0; kk < 16; kk++) {
            float4 av = *(float4*)&As[kk][ty * 4];
            float4 bv = *(float4*)&Bs[kk][tx * 4];
            float a_[4] = {av.x, av.y, av.z, av.w};
            float b_[4] = {bv.x, bv.y, bv.z, bv.w};
            #pragma unroll
            for (int i = 0; i < 4; i++)
                #pragma unroll
                for (int j = 0; j < 4; j++)
                    acc[i][j] += a_[i] * b_[j];
        }
        __syncthreads();
    }

    if (blockIdx.z == 0) {
        #pragma unroll
        for (int i = 0; i < 4; i++) {
            float4 v = make_float4(acc[i][0], acc[i][1], acc[i][2], acc[i][3]);
            *(float4*)&g_qh[(row0 + ty * 4 + i) * NH + col0 + tx * 4] = v;
        }
    } else {
        #pragma unroll
        for (int i = 0; i < 4; i++) {
            uint2 u;
            u.x = f2h2(acc[i][0], acc[i][1]);
            u.y = f2h2(acc[i][2], acc[i][3]);
            *(uint2*)&g_kh[(row0 + ty * 4 + i) * NH + col0 + tx * 4] = u;
        }
    }
}

// ---------------------------------------------------------------------------
// values f32 -> f16 (one-time): 1024 blocks x 256 threads, 1 float4 each.
// ---------------------------------------------------------------------------
__global__ __launch_bounds__(256) void convert_v_kernel(const float* __restrict__ values)
{
    int i = blockIdx.x * 256 + threadIdx.x;         // 0 .. 262143 float4s
    float4 v = *(const float4*)&values[i * 4];
    uint2 u;
    u.x = f2h2(v.x, v.y);
    u.y = f2h2(v.z, v.w);
    *(uint2*)&g_vh[i * 4] = u;
}

// ---------------------------------------------------------------------------
// Fused attention, LDS-minimized:
//  - kh/values tiles staged in smem as f16 with padded rows (ROWW words)
//  - q (f16x2) and wv (f32) in per-lane registers: lane owns h-slice h8*32..+32
//  - Phase A lane map: k2 = lane&3 (key in 4-key group), h8 = lane>>2
//    per group: 4x LDS.128, f16x2 add+tanh, f32 FFMA, 3 shfl reduce
//  - Phase C: half values, attn weights hoisted to regs, f32 accumulate
// 256 blocks x 256 threads = 8 warps = 8 queries of batch (blockIdx & 3).
// ---------------------------------------------------------------------------
__global__ __launch_bounds__(256) void attn_kernel(
    const float* __restrict__ wv,
    const int*   __restrict__ valid_lens,
    float*       __restrict__ out)
{
    __shared__ uint32_t tilew[32 * ROWW];   // 16896 B: kh tiles (A) / values tiles (C)
    __shared__ float attn_s[8 * NK];        // 16384 B

    const int t    = threadIdx.x;
    const int w    = t >> 5;
    const int lane = t & 31;
    const int k2   = lane & 3;
    const int h8   = lane >> 2;
    const int b    = blockIdx.x & 3;        // batch-interleaved
    const int qblk = blockIdx.x >> 2;       // 0..63
    const int vl   = valid_lens[b];         // uniform across block
    const int qrow = b * NQ + qblk * 8 + w;

    // ---------------- per-lane q (f16x2) + wv (f32) registers ----------------
    unsigned q2[16];
    float wvr[32];
    {
        const float* qp = &g_qh[qrow * NH + h8 * 32];
        const float* wp = &wv[h8 * 32];
        #pragma unroll
        for (int i = 0; i < 8; i++) {
            float4 qv = *(const float4*)&qp[i * 4];
            float4 w4 = *(const float4*)&wp[i * 4];
            q2[i * 2]     = f2h2(qv.x, qv.y);
            q2[i * 2 + 1] = f2h2(qv.z, qv.w);
            wvr[i * 4 + 0] = w4.x; wvr[i * 4 + 1] = w4.y;
            wvr[i * 4 + 2] = w4.z; wvr[i * 4 + 3] = w4.w;
        }
    }

    // ---------------- Phase A: scores -> attn_s ----------------
    const __half* khb = &g_kh[(b * NK) * NH];
    const int nTA = (vl + 31) >> 5;

    for (int tile = 0; tile < nTA; ++tile) {
        // stage 32 keys x 256 halfs (1024 uint4, 4/thread), padded rows
        const uint4* src = (const uint4*)(khb + tile * 32 * NH);
        #pragma unroll
        for (int r = 0; r < 4; ++r) {
            int i   = t + 256 * r;
            int row = i >> 5;
            int c   = i & 31;
            *(uint4*)&tilew[row * ROWW + c * 4] = src[row * 32 + c];
        }
        __syncthreads();

        #pragma unroll 2
        for (int g = 0; g < 8; ++g) {
            const uint32_t* kro = &tilew[(g * 4 + k2) * ROWW + h8 * 16];
            float acc = 0.f;
            #pragma unroll
            for (int j = 0; j < 4; ++j) {
                uint4 kv = *(const uint4*)&kro[j * 4];       // 8 halfs
                unsigned xs[4] = {kv.x, kv.y, kv.z, kv.w};
                #pragma unroll
                for (int i2 = 0; i2 < 4; ++i2) {
                    unsigned x  = hadd2_u(xs[i2], q2[j * 4 + i2]);
                    float2   f  = h2f2(tanh2_u(x));
                    acc += wvr[j * 8 + i2 * 2]     * f.x;
                    acc += wvr[j * 8 + i2 * 2 + 1] * f.y;
                }
            }
            acc += __shfl_xor_sync(0xffffffffu, acc, 4);     // reduce over h8
            acc += __shfl_xor_sync(0xffffffffu, acc, 8);
            acc += __shfl_xor_sync(0xffffffffu, acc, 16);
            if (lane < 4)
                attn_s[w * NK + tile * 32 + g * 4 + lane] = acc;
        }
        __syncthreads();                      // reads done before next stage
    }

    // ---------------- Phase B: masked softmax (f32, smem + shuffles) --------
    float mx = -1.0e30f;
    for (int i = 0; i < 16; i++) {
        int k = i * 32 + lane;
        float v = (k < vl) ? attn_s[w * NK + k] : -1.0e6f;
        mx = fmaxf(mx, v);
    }
    #pragma unroll
    for (int o = 16; o > 0; o >>= 1)
        mx = fmaxf(mx, __shfl_xor_sync(0xffffffffu, mx, o));

    float sum = 0.f;
    for (int i = 0; i < 16; i++) {
        int k = i * 32 + lane;
        float v = (k < vl) ? attn_s[w * NK + k] : -1.0e6f;
        float e = __expf(v - mx);             // masked -> exact 0
        sum += e;
        attn_s[w * NK + k] = e;               // unnormalized (warp-own row)
    }
    #pragma unroll
    for (int o = 16; o > 0; o >>= 1)
        sum += __shfl_xor_sync(0xffffffffu, sum, o);
    const float inv = 1.0f / sum;

    // ---------------- Phase C: out = attn @ values (f16 values) -------------
    const __half* vbh = &g_vh[(b * NK) * ND];
    const int nTC = (vl + 15) >> 4;
    float o0 = 0.f, o1 = 0.f, o2 = 0.f, o3 = 0.f;
    float o4 = 0.f, o5 = 0.f, o6 = 0.f, o7 = 0.f;

    for (int tile = 0; tile < nTC; ++tile) {
        __syncthreads();                      // prev tile reads done (A done via its syncs)
        // stage 16 keys x 256 halfs (512 uint4, 2/thread)
        const uint4* src = (const uint4*)(vbh + tile * 16 * ND);
        #pragma unroll
        for (int r = 0; r < 2; ++r) {
            int i   = t + 256 * r;
            int row = i >> 5;
            int c   = i & 31;
            *(uint4*)&tilew[row * ROWW + c * 4] = src[row * 32 + c];
        }
        __syncthreads();

        // hoist this tile's 16 attn weights into registers
        float at[16];
        #pragma unroll
        for (int i = 0; i < 4; i++) {
            float4 a4 = *(const float4*)&attn_s[w * NK + tile * 16 + i * 4];
            at[i * 4 + 0] = a4.x; at[i * 4 + 1] = a4.y;
            at[i * 4 + 2] = a4.z; at[i * 4 + 3] = a4.w;
        }

        #pragma unroll 4
        for (int kk = 0; kk < 16; ++kk) {
            uint4 vv = *(const uint4*)&tilew[kk * ROWW + lane * 4];   // 8 halfs: d = lane*8..+8
            float a = at[kk];
            float2 f0 = h2f2(vv.x);
            float2 f1 = h2f2(vv.y);
            float2 f2v = h2f2(vv.z);
            float2 f3 = h2f2(vv.w);
            o0 += a * f0.x; o1 += a * f0.y;
            o2 += a * f1.x; o3 += a * f1.y;
            o4 += a * f2v.x; o5 += a * f2v.y;
            o6 += a * f3.x; o7 += a * f3.y;
        }
    }

    float4 r0 = make_float4(o0 * inv, o1 * inv, o2 * inv, o3 * inv);
    float4 r1 = make_float4(o4 * inv, o5 * inv, o6 * inv, o7 * inv);
    *(float4*)&out[qrow * ND + lane * 8]     = r0;
    *(float4*)&out[qrow * ND + lane * 8 + 4] = r1;
}

// ---------------------------------------------------------------------------
extern "C" void kernel_launch(void* const* d_in, const int* in_sizes, int n_in,
                              void* d_out, int out_size)
{
    const float* queries = (const float*)d_in[0];
    const float* keys    = (const float*)d_in[1];
    const float* values  = (const float*)d_in[2];
    const float* Wq      = (const float*)d_in[3];
    const float* Wk      = (const float*)d_in[4];
    const float* wv      = (const float*)d_in[5];
    const int*   vlen    = (const int*)d_in[6];
    float* out = (float*)d_out;

    (void)in_sizes; (void)n_in; (void)out_size;

    dim3 pgrid(NH / 64, (NB * NQ) / 64, 2);
    proj_kernel<<<pgrid, 256>>>(queries, Wq, keys, Wk);
    convert_v_kernel<<<(NB * NK * ND) / 4 / 256, 256>>>(values);

    attn_kernel<<<(NB * NQ) / 8, 256>>>(wv, vlen, out);
}